// round 1
// baseline (speedup 1.0000x reference)
#include <cuda_runtime.h>

#define NC 32
#define NU 5
#define NV 5
#define NH 64
#define NW 64

#define TILE_H 16
#define TILE_W 32
#define HLp 18            // TILE_H + 2
#define WLp 34            // TILE_W + 2
#define PLANE (HLp * WLp) // 612
#define SXN (9 * PLANE)   // 5508
#define NWGT (4 * 27 * 8) // 864 weights per input channel
#define CHSTRIDE (NU * NV * NH * NW) // 102400

// Reorganized weights: [c][branch][tap][o], tap = (ka*3+kb)*3+kg
__device__ float g_wr[NC * NWGT];
__device__ float g_bias[32];
__device__ float g_slope[4];

__global__ void prep_kernel(const float* __restrict__ w0, const float* __restrict__ w1,
                            const float* __restrict__ w2, const float* __restrict__ w3,
                            const float* __restrict__ b0, const float* __restrict__ b1,
                            const float* __restrict__ b2, const float* __restrict__ b3,
                            const float* __restrict__ a0, const float* __restrict__ a1,
                            const float* __restrict__ a2, const float* __restrict__ a3)
{
    int t = blockIdx.x * blockDim.x + threadIdx.x;
    if (t < NC * NWGT) {
        int o   = t & 7;
        int tap = (t >> 3) % 27;
        int br  = (t / 216) & 3;
        int c   = t / 864;
        const float* w = (br == 0) ? w0 : (br == 1) ? w1 : (br == 2) ? w2 : w3;
        // source layout: w[o][c][tap] with tap over the branch's own (kd,kh,kw)
        g_wr[t] = w[(o * NC + c) * 27 + tap];
    }
    if (t < 32) {
        const float* b = (t < 8) ? b0 : (t < 16) ? b1 : (t < 24) ? b2 : b3;
        g_bias[t] = b[t & 7];
    }
    if (t < 4) {
        const float* a = (t == 0) ? a0 : (t == 1) ? a1 : (t == 2) ? a2 : a3;
        g_slope[t] = a[0];
    }
}

// Packed fp32x2 FMA (sm_100+): d = a*b + d
__device__ __forceinline__ void fma2(unsigned long long& acc,
                                     unsigned long long a, unsigned long long b) {
    asm("fma.rn.f32x2 %0, %1, %2, %0;" : "+l"(acc) : "l"(a), "l"(b));
}
__device__ __forceinline__ unsigned long long splat2(float v) {
    unsigned long long r;
    asm("mov.b64 %0, {%1, %1};" : "=l"(r) : "f"(v));
    return r;
}
__device__ __forceinline__ float2 unpack2(unsigned long long v) {
    float2 r;
    asm("mov.b64 {%0, %1}, %2;" : "=f"(r.x), "=f"(r.y) : "l"(v));
    return r;
}

__global__ __launch_bounds__(256, 2)
void fe_kernel(const float* __restrict__ x, float* __restrict__ out)
{
    __shared__ __align__(16) float s_x[SXN];   // 9 uv-planes x (18x34) halo tile
    __shared__ __align__(16) float s_w[NWGT];  // per-channel weights
    __shared__ float s_b[32];
    __shared__ float s_a[4];

    const int tid = threadIdx.x;
    const int wl  = tid & 31;      // 0..31 (w within tile)
    const int hl  = tid >> 5;      // 0..7  (two rows per thread: hl and hl+8)

    const int tile = blockIdx.x;               // 0..7 (2 w-tiles x 4 h-tiles)
    const int tw   = (tile & 1) * TILE_W;
    const int th   = (tile >> 1) * TILE_H;
    const int uv   = blockIdx.y;               // 0..24
    const int u    = uv / 5, v = uv % 5;
    const int b    = blockIdx.z;               // 0..7

    if (tid < 32) s_b[tid] = g_bias[tid];
    if (tid < 4)  s_a[tid] = g_slope[tid];

    // acc[point][pair]: pair j covers global out channels 2j, 2j+1
    unsigned long long acc[2][16];
    #pragma unroll
    for (int p = 0; p < 2; p++)
        #pragma unroll
        for (int j = 0; j < 16; j++) acc[p][j] = 0ull;

    const float* xb = x + (size_t)b * (NC * CHSTRIDE);

    #pragma unroll 1
    for (int c = 0; c < NC; c++) {
        const float* xc = xb + (size_t)c * CHSTRIDE;

        // stage this channel's 864 weights
        for (int i = tid; i < NWGT; i += 256)
            s_w[i] = g_wr[c * NWGT + i];

        // stage input tile: 3x3 uv-planes with (h,w) halo, zero-padded OOB
        for (int i = tid; i < SXN; i += 256) {
            int pidx = i / PLANE;
            int rem  = i - pidx * PLANE;
            int row  = rem / WLp;
            int col  = rem - row * WLp;
            int pa = pidx / 3, pb = pidx - pa * 3;
            int gu = u + pa - 1;
            int gv = v + pb - 1;
            int gh = th + row - 1;
            int gw = tw + col - 1;
            float val = 0.f;
            if ((unsigned)gu < NU && (unsigned)gv < NV &&
                (unsigned)gh < NH && (unsigned)gw < NW)
                val = __ldg(xc + ((gu * NV + gv) * NH + gh) * NW + gw);
            s_x[i] = val;
        }
        __syncthreads();

        // ---- uvx (taps over U,V,H; w fixed) + uvy (taps over U,V,W; h fixed) ----
        #pragma unroll
        for (int ka = 0; ka < 3; ka++) {
            #pragma unroll
            for (int kb = 0; kb < 3; kb++) {
                const float* pl = s_x + (ka * 3 + kb) * PLANE;
                #pragma unroll
                for (int kg = 0; kg < 3; kg++) {
                    const int tap = (ka * 3 + kb) * 3 + kg;
                    {   // uvx -> channels 0..7 (acc pairs 0..3)
                        const float* wp = s_w + tap * 8;
                        ulonglong2 w01 = *(const ulonglong2*)wp;
                        ulonglong2 w23 = *(const ulonglong2*)(wp + 4);
                        #pragma unroll
                        for (int p = 0; p < 2; p++) {
                            unsigned long long xx =
                                splat2(pl[(hl + p * 8 + kg) * WLp + (wl + 1)]);
                            fma2(acc[p][0], xx, w01.x);
                            fma2(acc[p][1], xx, w01.y);
                            fma2(acc[p][2], xx, w23.x);
                            fma2(acc[p][3], xx, w23.y);
                        }
                    }
                    {   // uvy -> channels 8..15 (acc pairs 4..7)
                        const float* wp = s_w + 216 + tap * 8;
                        ulonglong2 w01 = *(const ulonglong2*)wp;
                        ulonglong2 w23 = *(const ulonglong2*)(wp + 4);
                        #pragma unroll
                        for (int p = 0; p < 2; p++) {
                            unsigned long long xx =
                                splat2(pl[(hl + p * 8 + 1) * WLp + (wl + kg)]);
                            fma2(acc[p][4], xx, w01.x);
                            fma2(acc[p][5], xx, w01.y);
                            fma2(acc[p][6], xx, w23.x);
                            fma2(acc[p][7], xx, w23.y);
                        }
                    }
                }
            }
        }

        // ---- uxy (taps over U,H,W; v fixed -> plane (ka,1)) ----
        #pragma unroll
        for (int ka = 0; ka < 3; ka++) {
            const float* pl = s_x + (ka * 3 + 1) * PLANE;
            #pragma unroll
            for (int kb = 0; kb < 3; kb++) {
                #pragma unroll
                for (int kg = 0; kg < 3; kg++) {
                    const int tap = (ka * 3 + kb) * 3 + kg;
                    const float* wp = s_w + 432 + tap * 8;
                    ulonglong2 w01 = *(const ulonglong2*)wp;
                    ulonglong2 w23 = *(const ulonglong2*)(wp + 4);
                    #pragma unroll
                    for (int p = 0; p < 2; p++) {
                        unsigned long long xx =
                            splat2(pl[(hl + p * 8 + kb) * WLp + (wl + kg)]);
                        fma2(acc[p][8],  xx, w01.x);
                        fma2(acc[p][9],  xx, w01.y);
                        fma2(acc[p][10], xx, w23.x);
                        fma2(acc[p][11], xx, w23.y);
                    }
                }
            }
        }

        // ---- vxy (taps over V,H,W; u fixed -> plane (1,ka)) ----
        #pragma unroll
        for (int ka = 0; ka < 3; ka++) {
            const float* pl = s_x + (3 + ka) * PLANE;
            #pragma unroll
            for (int kb = 0; kb < 3; kb++) {
                #pragma unroll
                for (int kg = 0; kg < 3; kg++) {
                    const int tap = (ka * 3 + kb) * 3 + kg;
                    const float* wp = s_w + 648 + tap * 8;
                    ulonglong2 w01 = *(const ulonglong2*)wp;
                    ulonglong2 w23 = *(const ulonglong2*)(wp + 4);
                    #pragma unroll
                    for (int p = 0; p < 2; p++) {
                        unsigned long long xx =
                            splat2(pl[(hl + p * 8 + kb) * WLp + (wl + kg)]);
                        fma2(acc[p][12], xx, w01.x);
                        fma2(acc[p][13], xx, w01.y);
                        fma2(acc[p][14], xx, w23.x);
                        fma2(acc[p][15], xx, w23.y);
                    }
                }
            }
        }
        __syncthreads();
    }

    // ---- epilogue: bias + PReLU + store ----
    const size_t base0 = (size_t)b * 32 * CHSTRIDE +
                         (size_t)(u * 5 + v) * (NH * NW) + (size_t)(tw + wl);
    #pragma unroll
    for (int p = 0; p < 2; p++) {
        const int h = th + hl + p * 8;
        const size_t base = base0 + (size_t)h * NW;
        #pragma unroll
        for (int j = 0; j < 16; j++) {
            const int oc = j * 2;
            const int br = j >> 2;
            float2 y = unpack2(acc[p][j]);
            float slope = s_a[br];
            float y0 = y.x + s_b[oc];
            float y1 = y.y + s_b[oc + 1];
            y0 = (y0 >= 0.f) ? y0 : slope * y0;
            y1 = (y1 >= 0.f) ? y1 : slope * y1;
            out[base + (size_t)oc * CHSTRIDE]       = y0;
            out[base + (size_t)(oc + 1) * CHSTRIDE] = y1;
        }
    }
}

extern "C" void kernel_launch(void* const* d_in, const int* in_sizes, int n_in,
                              void* d_out, int out_size)
{
    const float* x = (const float*)d_in[0];
    // inputs: x, (w,b,a) x {uvx, uvy, uxy, vxy}
    prep_kernel<<<(NC * NWGT + 255) / 256, 256>>>(
        (const float*)d_in[1], (const float*)d_in[4],
        (const float*)d_in[7], (const float*)d_in[10],
        (const float*)d_in[2], (const float*)d_in[5],
        (const float*)d_in[8], (const float*)d_in[11],
        (const float*)d_in[3], (const float*)d_in[6],
        (const float*)d_in[9], (const float*)d_in[12]);

    dim3 grid(8, 25, 8);   // (hw tiles, uv, batch)
    fe_kernel<<<grid, 256>>>(x, (float*)d_out);
}

// round 5
// speedup vs baseline: 1.3251x; 1.3251x over previous
#include <cuda_runtime.h>
#include <cstdint>

#define NC 32
#define NU 5
#define NV 5
#define NH 64
#define NW 64

#define TILE_H 8
#define ROWF 72                 // smem row pitch (floats): 4 pad | 64 data | 4 pad
#define ROWS 10                 // TILE_H + 2
#define PLF (ROWS * ROWF)       // 720 floats per uv-plane
#define XF (9 * PLF)            // 6480 floats per x stage
#define WF (4 * 27 * 8)         // 864 weights per channel
#define SMEM_FLOATS (2 * XF + 2 * WF)        // 14688
#define SMEM_BYTES  (SMEM_FLOATS * 4)        // 58752
#define CHSTRIDE (NU * NV * NH * NW)         // 102400

// Reorganized weights: [c][branch][tap][o], tap = (ka*3+kb)*3+kg
__device__ __align__(128) float g_wr[NC * WF];
__device__ float g_bias[32];
__device__ float g_slope[4];

__global__ void prep_kernel(const float* __restrict__ w0, const float* __restrict__ w1,
                            const float* __restrict__ w2, const float* __restrict__ w3,
                            const float* __restrict__ b0, const float* __restrict__ b1,
                            const float* __restrict__ b2, const float* __restrict__ b3,
                            const float* __restrict__ a0, const float* __restrict__ a1,
                            const float* __restrict__ a2, const float* __restrict__ a3)
{
    int t = blockIdx.x * blockDim.x + threadIdx.x;
    if (t < NC * WF) {
        int o   = t & 7;
        int tap = (t >> 3) % 27;
        int br  = (t / 216) & 3;
        int c   = t / 864;
        const float* w = (br == 0) ? w0 : (br == 1) ? w1 : (br == 2) ? w2 : w3;
        g_wr[t] = w[(o * NC + c) * 27 + tap];
    }
    if (t < 32) {
        const float* b = (t < 8) ? b0 : (t < 16) ? b1 : (t < 24) ? b2 : b3;
        g_bias[t] = b[t & 7];
    }
    if (t < 4) {
        const float* a = (t == 0) ? a0 : (t == 1) ? a1 : (t == 2) ? a2 : a3;
        g_slope[t] = a[0];
    }
}

// ---------- helpers ----------
__device__ __forceinline__ uint32_t smem_u32(const void* p) {
    uint32_t a;
    asm("{ .reg .u64 t; cvta.to.shared.u64 t, %1; cvt.u32.u64 %0, t; }" : "=r"(a) : "l"(p));
    return a;
}
__device__ __forceinline__ void cp16(uint32_t dst, const void* src) {
    asm volatile("cp.async.cg.shared.global [%0], [%1], 16;" :: "r"(dst), "l"(src) : "memory");
}
__device__ __forceinline__ void cp_commit() {
    asm volatile("cp.async.commit_group;" ::: "memory");
}
__device__ __forceinline__ void cp_wait1() {
    asm volatile("cp.async.wait_group 1;" ::: "memory");
}
__device__ __forceinline__ void cp_wait0() {
    asm volatile("cp.async.wait_group 0;" ::: "memory");
}

// Packed fp32x2 FMA (sm_100+): d = a*b + d
__device__ __forceinline__ void fma2(unsigned long long& acc,
                                     unsigned long long a, unsigned long long b) {
    asm("fma.rn.f32x2 %0, %1, %2, %0;" : "+l"(acc) : "l"(a), "l"(b));
}
__device__ __forceinline__ unsigned long long splat2(float v) {
    unsigned long long r;
    asm("mov.b64 %0, {%1, %1};" : "=l"(r) : "f"(v));
    return r;
}
__device__ __forceinline__ float2 unpack2(unsigned long long v) {
    float2 r;
    asm("mov.b64 {%0, %1}, %2;" : "=f"(r.x), "=f"(r.y) : "l"(v));
    return r;
}

// ---------- staging: one channel into stage buffers via cp.async ----------
// x rows: 90 rows (9 uv-planes x 10 h-rows) of 64 floats = 16 chunks each.
// OOB rows are skipped (smem pre-zeroed once; OOB pattern is channel-invariant).
__device__ __forceinline__ void stage_channel(const float* __restrict__ xc, int c,
                                              uint32_t sx_u32, uint32_t sw_u32,
                                              int u, int v, int th, int tid)
{
    #pragma unroll
    for (int i = 0; i < 6; i++) {
        int k = tid + i * 256;
        if (i < 5 || k < 1440) {
            int row   = k >> 4;
            int chunk = k & 15;
            int pidx  = row / 10;
            int r     = row - pidx * 10;
            int pa    = pidx / 3;
            int pb    = pidx - pa * 3;
            int gu = u + pa - 1;
            int gv = v + pb - 1;
            int gh = th + r - 1;
            if ((unsigned)gu < NU && (unsigned)gv < NV && (unsigned)gh < NH) {
                const float* src = xc + (((gu * 5 + gv) * NH + gh) << 6) + chunk * 4;
                uint32_t dst = sx_u32 + (uint32_t)(row * ROWF + 4 + chunk * 4) * 4u;
                cp16(dst, src);
            }
        }
    }
    if (tid < 216) {
        const float* src = g_wr + c * WF + tid * 4;
        cp16(sw_u32 + (uint32_t)tid * 16u, src);
    }
}

// ---------- compute: one input channel, all 4 branches ----------
__device__ __forceinline__ void compute_channel(const float* __restrict__ s_x,
                                                const float* __restrict__ s_w,
                                                int hl, int wl,
                                                unsigned long long (&acc)[2][16])
{
    // ---- uvx (taps over U,V,H) + uvy (taps over U,V,W) ----
    #pragma unroll
    for (int ka = 0; ka < 3; ka++) {
        #pragma unroll
        for (int kb = 0; kb < 3; kb++) {
            const float* pl = s_x + (ka * 3 + kb) * PLF;
            #pragma unroll
            for (int kg = 0; kg < 3; kg++) {
                const int tap = (ka * 3 + kb) * 3 + kg;
                {   // uvx -> acc pairs 0..3
                    const float* wp = s_w + tap * 8;
                    ulonglong2 w01 = *(const ulonglong2*)wp;
                    ulonglong2 w23 = *(const ulonglong2*)(wp + 4);
                    #pragma unroll
                    for (int p = 0; p < 2; p++) {
                        unsigned long long xx =
                            splat2(pl[(hl + p * 4 + kg) * ROWF + (wl + 4)]);
                        fma2(acc[p][0], xx, w01.x);
                        fma2(acc[p][1], xx, w01.y);
                        fma2(acc[p][2], xx, w23.x);
                        fma2(acc[p][3], xx, w23.y);
                    }
                }
                {   // uvy -> acc pairs 4..7
                    const float* wp = s_w + 216 + tap * 8;
                    ulonglong2 w01 = *(const ulonglong2*)wp;
                    ulonglong2 w23 = *(const ulonglong2*)(wp + 4);
                    #pragma unroll
                    for (int p = 0; p < 2; p++) {
                        unsigned long long xx =
                            splat2(pl[(hl + p * 4 + 1) * ROWF + (wl + 3 + kg)]);
                        fma2(acc[p][4], xx, w01.x);
                        fma2(acc[p][5], xx, w01.y);
                        fma2(acc[p][6], xx, w23.x);
                        fma2(acc[p][7], xx, w23.y);
                    }
                }
            }
        }
    }
    // ---- uxy (v fixed -> plane (ka,1)) ----
    #pragma unroll
    for (int ka = 0; ka < 3; ka++) {
        const float* pl = s_x + (ka * 3 + 1) * PLF;
        #pragma unroll
        for (int kb = 0; kb < 3; kb++) {
            #pragma unroll
            for (int kg = 0; kg < 3; kg++) {
                const int tap = (ka * 3 + kb) * 3 + kg;
                const float* wp = s_w + 432 + tap * 8;
                ulonglong2 w01 = *(const ulonglong2*)wp;
                ulonglong2 w23 = *(const ulonglong2*)(wp + 4);
                #pragma unroll
                for (int p = 0; p < 2; p++) {
                    unsigned long long xx =
                        splat2(pl[(hl + p * 4 + kb) * ROWF + (wl + 3 + kg)]);
                    fma2(acc[p][8],  xx, w01.x);
                    fma2(acc[p][9],  xx, w01.y);
                    fma2(acc[p][10], xx, w23.x);
                    fma2(acc[p][11], xx, w23.y);
                }
            }
        }
    }
    // ---- vxy (u fixed -> plane (1,ka)) ----
    #pragma unroll
    for (int ka = 0; ka < 3; ka++) {
        const float* pl = s_x + (3 + ka) * PLF;
        #pragma unroll
        for (int kb = 0; kb < 3; kb++) {
            #pragma unroll
            for (int kg = 0; kg < 3; kg++) {
                const int tap = (ka * 3 + kb) * 3 + kg;
                const float* wp = s_w + 648 + tap * 8;
                ulonglong2 w01 = *(const ulonglong2*)wp;
                ulonglong2 w23 = *(const ulonglong2*)(wp + 4);
                #pragma unroll
                for (int p = 0; p < 2; p++) {
                    unsigned long long xx =
                        splat2(pl[(hl + p * 4 + kb) * ROWF + (wl + 3 + kg)]);
                    fma2(acc[p][12], xx, w01.x);
                    fma2(acc[p][13], xx, w01.y);
                    fma2(acc[p][14], xx, w23.x);
                    fma2(acc[p][15], xx, w23.y);
                }
            }
        }
    }
}

// ===================== main kernel =====================
__global__ __launch_bounds__(256, 2)
void fe_kernel(const float* __restrict__ x, float* __restrict__ out)
{
    extern __shared__ __align__(16) float sm[];
    float* sx0 = sm;
    float* sx1 = sm + XF;
    float* sw0 = sm + 2 * XF;
    float* sw1 = sm + 2 * XF + WF;
    const uint32_t sx_u[2] = { smem_u32(sx0), smem_u32(sx1) };
    const uint32_t sw_u[2] = { smem_u32(sw0), smem_u32(sw1) };
    const float* sx_p[2] = { sx0, sx1 };
    const float* sw_p[2] = { sw0, sw1 };

    const int tid = threadIdx.x;
    const int wl  = tid & 63;      // 0..63 (w)
    const int hl  = tid >> 6;      // 0..3  (two rows per thread: hl, hl+4)

    const int th = blockIdx.x * TILE_H;   // 0..56
    const int uv = blockIdx.y;            // 0..24
    const int u  = uv / 5, v = uv % 5;
    const int b  = blockIdx.z;            // 0..7

    // one-time zero (provides halo cols + channel-invariant OOB rows)
    float4* z = (float4*)sm;
    #pragma unroll
    for (int i = tid; i < SMEM_FLOATS / 4; i += 256)
        z[i] = make_float4(0.f, 0.f, 0.f, 0.f);
    __syncthreads();

    const float* xb = x + (size_t)b * (NC * CHSTRIDE);

    stage_channel(xb, 0, sx_u[0], sw_u[0], u, v, th, tid);
    cp_commit();

    unsigned long long acc[2][16];
    #pragma unroll
    for (int p = 0; p < 2; p++)
        #pragma unroll
        for (int j = 0; j < 16; j++) acc[p][j] = 0ull;

    #pragma unroll 1
    for (int c = 0; c < NC; c++) {
        const int s = c & 1;
        if (c < NC - 1) {
            stage_channel(xb + (size_t)(c + 1) * CHSTRIDE, c + 1,
                          sx_u[s ^ 1], sw_u[s ^ 1], u, v, th, tid);
            cp_commit();
            cp_wait1();
        } else {
            cp_wait0();
        }
        __syncthreads();

        compute_channel(sx_p[s], sw_p[s], hl, wl, acc);
        __syncthreads();
    }

    // ---- epilogue: bias + PReLU + store ----
    const size_t base0 = (size_t)b * 32 * CHSTRIDE +
                         (size_t)(u * 5 + v) * (NH * NW) + (size_t)wl;
    #pragma unroll
    for (int p = 0; p < 2; p++) {
        const int h = th + hl + p * 4;
        const size_t base = base0 + (size_t)h * NW;
        #pragma unroll
        for (int j = 0; j < 16; j++) {
            const int oc = j * 2;
            const int br = j >> 2;
            float2 y = unpack2(acc[p][j]);
            float slope = g_slope[br];
            float y0 = y.x + g_bias[oc];
            float y1 = y.y + g_bias[oc + 1];
            y0 = (y0 >= 0.f) ? y0 : slope * y0;
            y1 = (y1 >= 0.f) ? y1 : slope * y1;
            out[base + (size_t)oc * CHSTRIDE]       = y0;
            out[base + (size_t)(oc + 1) * CHSTRIDE] = y1;
        }
    }
}

extern "C" void kernel_launch(void* const* d_in, const int* in_sizes, int n_in,
                              void* d_out, int out_size)
{
    const float* x = (const float*)d_in[0];

    prep_kernel<<<(NC * WF + 255) / 256, 256>>>(
        (const float*)d_in[1], (const float*)d_in[4],
        (const float*)d_in[7], (const float*)d_in[10],
        (const float*)d_in[2], (const float*)d_in[5],
        (const float*)d_in[8], (const float*)d_in[11],
        (const float*)d_in[3], (const float*)d_in[6],
        (const float*)d_in[9], (const float*)d_in[12]);

    static bool attr_set = false;
    if (!attr_set) {
        cudaFuncSetAttribute(fe_kernel, cudaFuncAttributeMaxDynamicSharedMemorySize,
                             SMEM_BYTES);
        attr_set = true;
    }

    dim3 grid(8, 25, 8);   // (h tiles, uv, batch)
    fe_kernel<<<grid, 256, SMEM_BYTES>>>(x, (float*)d_out);
}

// round 6
// speedup vs baseline: 2.1169x; 1.5976x over previous
#include <cuda_runtime.h>
#include <cstdint>

#define NC 32
#define NU 5
#define NV 5
#define NH 64
#define NW 64

#define TILE_H 8
#define ROWF 72                 // smem row pitch (floats): 4 pad | 64 data | 4 pad
#define ROWS 10                 // TILE_H + 2
#define PLF (ROWS * ROWF)       // 720 floats per uv-plane
#define XF (9 * PLF)            // 6480 floats per x stage
#define WF (4 * 27 * 8)         // 864 weights per channel
#define SMEM_FLOATS (2 * XF + 2 * WF)        // 14688
#define SMEM_BYTES  (SMEM_FLOATS * 4)        // 58752
#define CHSTRIDE (NU * NV * NH * NW)         // 102400

// Reorganized weights: [c][branch][tap][o], tap = (ka*3+kb)*3+kg
__device__ __align__(128) float g_wr[NC * WF];
__device__ float g_bias[32];
__device__ float g_slope[4];

__global__ void prep_kernel(const float* __restrict__ w0, const float* __restrict__ w1,
                            const float* __restrict__ w2, const float* __restrict__ w3,
                            const float* __restrict__ b0, const float* __restrict__ b1,
                            const float* __restrict__ b2, const float* __restrict__ b3,
                            const float* __restrict__ a0, const float* __restrict__ a1,
                            const float* __restrict__ a2, const float* __restrict__ a3)
{
    int t = blockIdx.x * blockDim.x + threadIdx.x;
    if (t < NC * WF) {
        int o   = t & 7;
        int tap = (t >> 3) % 27;
        int br  = (t / 216) & 3;
        int c   = t / 864;
        const float* w = (br == 0) ? w0 : (br == 1) ? w1 : (br == 2) ? w2 : w3;
        g_wr[t] = w[(o * NC + c) * 27 + tap];
    }
    if (t < 32) {
        const float* b = (t < 8) ? b0 : (t < 16) ? b1 : (t < 24) ? b2 : b3;
        g_bias[t] = b[t & 7];
    }
    if (t < 4) {
        const float* a = (t == 0) ? a0 : (t == 1) ? a1 : (t == 2) ? a2 : a3;
        g_slope[t] = a[0];
    }
}

// ---------- helpers ----------
__device__ __forceinline__ uint32_t smem_u32(const void* p) {
    uint32_t a;
    asm("{ .reg .u64 t; cvta.to.shared.u64 t, %1; cvt.u32.u64 %0, t; }" : "=r"(a) : "l"(p));
    return a;
}
__device__ __forceinline__ void cp16(uint32_t dst, const void* src) {
    asm volatile("cp.async.cg.shared.global [%0], [%1], 16;" :: "r"(dst), "l"(src) : "memory");
}
__device__ __forceinline__ void cp_commit() {
    asm volatile("cp.async.commit_group;" ::: "memory");
}
__device__ __forceinline__ void cp_wait1() {
    asm volatile("cp.async.wait_group 1;" ::: "memory");
}
__device__ __forceinline__ void cp_wait0() {
    asm volatile("cp.async.wait_group 0;" ::: "memory");
}

// Packed fp32x2 FMA (sm_100+): d = a*b + d
__device__ __forceinline__ void fma2(unsigned long long& acc,
                                     unsigned long long a, unsigned long long b) {
    asm("fma.rn.f32x2 %0, %1, %2, %0;" : "+l"(acc) : "l"(a), "l"(b));
}
__device__ __forceinline__ unsigned long long splat2(float v) {
    unsigned long long r;
    asm("mov.b64 %0, {%1, %1};" : "=l"(r) : "f"(v));
    return r;
}
__device__ __forceinline__ float2 unpack2(unsigned long long v) {
    float2 r;
    asm("mov.b64 {%0, %1}, %2;" : "=f"(r.x), "=f"(r.y) : "l"(v));
    return r;
}

// ---------- staging: one channel into stage buffers via cp.async ----------
__device__ __forceinline__ void stage_channel(const float* __restrict__ xc, int c,
                                              uint32_t sx_u32, uint32_t sw_u32,
                                              int u, int v, int th, int tid)
{
    #pragma unroll
    for (int i = 0; i < 6; i++) {
        int k = tid + i * 256;
        if (i < 5 || k < 1440) {
            int row   = k >> 4;
            int chunk = k & 15;
            int pidx  = row / 10;
            int r     = row - pidx * 10;
            int pa    = pidx / 3;
            int pb    = pidx - pa * 3;
            int gu = u + pa - 1;
            int gv = v + pb - 1;
            int gh = th + r - 1;
            if ((unsigned)gu < NU && (unsigned)gv < NV && (unsigned)gh < NH) {
                const float* src = xc + (((gu * 5 + gv) * NH + gh) << 6) + chunk * 4;
                uint32_t dst = sx_u32 + (uint32_t)(row * ROWF + 4 + chunk * 4) * 4u;
                cp16(dst, src);
            }
        }
    }
    if (tid < 216) {
        const float* src = g_wr + c * WF + tid * 4;
        cp16(sw_u32 + (uint32_t)tid * 16u, src);
    }
}

// ===== per-branch compute: 8 h-points x 8 output channels per thread =====
// acc[p][j]: point p (h = th+p), channel pair (2j, 2j+1) of this branch.

// uvx: taps (u, v, h); x = plane(ka,kb), row p+kg, col wl+4
__device__ __forceinline__ void comp_uvx(const float* __restrict__ s_x,
                                         const float* __restrict__ s_w,
                                         int wl, unsigned long long (&acc)[8][4])
{
    #pragma unroll
    for (int ab = 0; ab < 9; ab++) {
        const float* col = s_x + ab * PLF + (wl + 4);
        unsigned long long xs[10];
        #pragma unroll
        for (int r = 0; r < 10; r++) xs[r] = splat2(col[r * ROWF]);
        #pragma unroll
        for (int kg = 0; kg < 3; kg++) {
            const float* wp = s_w + (ab * 3 + kg) * 8;
            ulonglong2 w01 = *(const ulonglong2*)wp;
            ulonglong2 w23 = *(const ulonglong2*)(wp + 4);
            #pragma unroll
            for (int p = 0; p < 8; p++) {
                unsigned long long xx = xs[p + kg];
                fma2(acc[p][0], xx, w01.x);
                fma2(acc[p][1], xx, w01.y);
                fma2(acc[p][2], xx, w23.x);
                fma2(acc[p][3], xx, w23.y);
            }
        }
    }
}

// uvy: taps (u, v, w); x = plane(ka,kb), row p+1, col wl+3+kg
__device__ __forceinline__ void comp_uvy(const float* __restrict__ s_x,
                                         const float* __restrict__ s_w,
                                         int wl, unsigned long long (&acc)[8][4])
{
    #pragma unroll
    for (int ab = 0; ab < 9; ab++) {
        const float* plb = s_x + ab * PLF;
        #pragma unroll
        for (int kg = 0; kg < 3; kg++) {
            const float* col = plb + (wl + 3 + kg);
            unsigned long long xs[8];
            #pragma unroll
            for (int p = 0; p < 8; p++) xs[p] = splat2(col[(p + 1) * ROWF]);
            const float* wp = s_w + 216 + (ab * 3 + kg) * 8;
            ulonglong2 w01 = *(const ulonglong2*)wp;
            ulonglong2 w23 = *(const ulonglong2*)(wp + 4);
            #pragma unroll
            for (int p = 0; p < 8; p++) {
                unsigned long long xx = xs[p];
                fma2(acc[p][0], xx, w01.x);
                fma2(acc[p][1], xx, w01.y);
                fma2(acc[p][2], xx, w23.x);
                fma2(acc[p][3], xx, w23.y);
            }
        }
    }
}

// uxy: taps (u, h, w); plane (ka,1); x row p+kb, col wl+3+kg
// vxy: taps (v, h, w); plane (1,ka) -> pass plane base + weight base
__device__ __forceinline__ void comp_hw(const float* __restrict__ s_x,
                                        const float* __restrict__ s_w,
                                        int wl, int plane_step_base, int plane_step,
                                        int wbase, unsigned long long (&acc)[8][4])
{
    #pragma unroll
    for (int ka = 0; ka < 3; ka++) {
        const float* plb = s_x + (plane_step_base + ka * plane_step) * PLF;
        #pragma unroll
        for (int kg = 0; kg < 3; kg++) {
            const float* col = plb + (wl + 3 + kg);
            unsigned long long xs[10];
            #pragma unroll
            for (int r = 0; r < 10; r++) xs[r] = splat2(col[r * ROWF]);
            #pragma unroll
            for (int kb = 0; kb < 3; kb++) {
                const float* wp = s_w + wbase + ((ka * 3 + kb) * 3 + kg) * 8;
                ulonglong2 w01 = *(const ulonglong2*)wp;
                ulonglong2 w23 = *(const ulonglong2*)(wp + 4);
                #pragma unroll
                for (int p = 0; p < 8; p++) {
                    unsigned long long xx = xs[p + kb];
                    fma2(acc[p][0], xx, w01.x);
                    fma2(acc[p][1], xx, w01.y);
                    fma2(acc[p][2], xx, w23.x);
                    fma2(acc[p][3], xx, w23.y);
                }
            }
        }
    }
}

// ===================== main kernel =====================
__global__ __launch_bounds__(256, 2)
void fe_kernel(const float* __restrict__ x, float* __restrict__ out)
{
    extern __shared__ __align__(16) float sm[];
    float* sx0 = sm;
    float* sx1 = sm + XF;
    float* sw0 = sm + 2 * XF;
    float* sw1 = sm + 2 * XF + WF;
    const uint32_t sx_u[2] = { smem_u32(sx0), smem_u32(sx1) };
    const uint32_t sw_u[2] = { smem_u32(sw0), smem_u32(sw1) };
    const float* sx_p[2] = { sx0, sx1 };
    const float* sw_p[2] = { sw0, sw1 };

    const int tid = threadIdx.x;
    const int g   = tid >> 6;      // branch group 0..3 (2 warps each)
    const int wl  = tid & 63;      // w column 0..63

    const int th = blockIdx.x * TILE_H;   // 0..56
    const int uv = blockIdx.y;            // 0..24
    const int u  = uv / 5, v = uv % 5;
    const int b  = blockIdx.z;            // 0..7

    // one-time zero (halo cols + channel-invariant OOB rows)
    float4* z = (float4*)sm;
    #pragma unroll
    for (int i = tid; i < SMEM_FLOATS / 4; i += 256)
        z[i] = make_float4(0.f, 0.f, 0.f, 0.f);
    __syncthreads();

    const float* xb = x + (size_t)b * (NC * CHSTRIDE);

    stage_channel(xb, 0, sx_u[0], sw_u[0], u, v, th, tid);
    cp_commit();

    unsigned long long acc[8][4];
    #pragma unroll
    for (int p = 0; p < 8; p++)
        #pragma unroll
        for (int j = 0; j < 4; j++) acc[p][j] = 0ull;

    #pragma unroll 1
    for (int c = 0; c < NC; c++) {
        const int s = c & 1;
        if (c < NC - 1) {
            stage_channel(xb + (size_t)(c + 1) * CHSTRIDE, c + 1,
                          sx_u[s ^ 1], sw_u[s ^ 1], u, v, th, tid);
            cp_commit();
            cp_wait1();
        } else {
            cp_wait0();
        }
        __syncthreads();

        if (g == 0)      comp_uvx(sx_p[s], sw_p[s], wl, acc);
        else if (g == 1) comp_uvy(sx_p[s], sw_p[s], wl, acc);
        else if (g == 2) comp_hw(sx_p[s], sw_p[s], wl, 1, 3, 432, acc); // uxy: planes (ka,1)
        else             comp_hw(sx_p[s], sw_p[s], wl, 3, 1, 648, acc); // vxy: planes (1,ka)
        __syncthreads();
    }

    // ---- epilogue: bias + PReLU + store ----
    const float slope = g_slope[g];
    const size_t base0 = (size_t)b * 32 * CHSTRIDE + (size_t)(g * 8) * CHSTRIDE +
                         (size_t)uv * (NH * NW) + (size_t)th * NW + (size_t)wl;
    #pragma unroll
    for (int j = 0; j < 4; j++) {
        const int oc = j * 2;
        const float b0 = g_bias[g * 8 + oc];
        const float b1 = g_bias[g * 8 + oc + 1];
        const size_t cb0 = base0 + (size_t)oc * CHSTRIDE;
        const size_t cb1 = base0 + (size_t)(oc + 1) * CHSTRIDE;
        #pragma unroll
        for (int p = 0; p < 8; p++) {
            float2 y = unpack2(acc[p][j]);
            float y0 = y.x + b0;
            float y1 = y.y + b1;
            y0 = (y0 >= 0.f) ? y0 : slope * y0;
            y1 = (y1 >= 0.f) ? y1 : slope * y1;
            out[cb0 + (size_t)p * NW] = y0;
            out[cb1 + (size_t)p * NW] = y1;
        }
    }
}

extern "C" void kernel_launch(void* const* d_in, const int* in_sizes, int n_in,
                              void* d_out, int out_size)
{
    const float* x = (const float*)d_in[0];

    prep_kernel<<<(NC * WF + 255) / 256, 256>>>(
        (const float*)d_in[1], (const float*)d_in[4],
        (const float*)d_in[7], (const float*)d_in[10],
        (const float*)d_in[2], (const float*)d_in[5],
        (const float*)d_in[8], (const float*)d_in[11],
        (const float*)d_in[3], (const float*)d_in[6],
        (const float*)d_in[9], (const float*)d_in[12]);

    static bool attr_set = false;
    if (!attr_set) {
        cudaFuncSetAttribute(fe_kernel, cudaFuncAttributeMaxDynamicSharedMemorySize,
                             SMEM_BYTES);
        attr_set = true;
    }

    dim3 grid(8, 25, 8);   // (h tiles, uv, batch)
    fe_kernel<<<grid, 256, SMEM_BYTES>>>(x, (float*)d_out);
}

// round 7
// speedup vs baseline: 2.1643x; 1.0224x over previous
#include <cuda_runtime.h>
#include <cstdint>

#define NC 32
#define NU 5
#define NV 5
#define NH 64
#define NW 64

#define TILE_H 8
#define TILE_W 32
#define ROWF 40                 // smem row pitch (floats); col j holds w = tw-4+j
#define ROWS 10                 // TILE_H + 2
#define PLF (ROWS * ROWF)       // 400 floats per uv-plane
#define XF (9 * PLF)            // 3600 floats per x stage
#define WF (4 * 27 * 8)         // 864 weights per channel
#define CHSTRIDE (NU * NV * NH * NW) // 102400

// Reorganized weights: [c][branch][tap][o], tap = (ka*3+kb)*3+kg
__device__ __align__(128) float g_wr[NC * WF];
__device__ float g_bias[32];
__device__ float g_slope[4];

__global__ void prep_kernel(const float* __restrict__ w0, const float* __restrict__ w1,
                            const float* __restrict__ w2, const float* __restrict__ w3,
                            const float* __restrict__ b0, const float* __restrict__ b1,
                            const float* __restrict__ b2, const float* __restrict__ b3,
                            const float* __restrict__ a0, const float* __restrict__ a1,
                            const float* __restrict__ a2, const float* __restrict__ a3)
{
    int t = blockIdx.x * blockDim.x + threadIdx.x;
    if (t < NC * WF) {
        int o   = t & 7;
        int tap = (t >> 3) % 27;
        int br  = (t / 216) & 3;
        int c   = t / 864;
        const float* w = (br == 0) ? w0 : (br == 1) ? w1 : (br == 2) ? w2 : w3;
        g_wr[t] = w[(o * NC + c) * 27 + tap];
    }
    if (t < 32) {
        const float* b = (t < 8) ? b0 : (t < 16) ? b1 : (t < 24) ? b2 : b3;
        g_bias[t] = b[t & 7];
    }
    if (t < 4) {
        const float* a = (t == 0) ? a0 : (t == 1) ? a1 : (t == 2) ? a2 : a3;
        g_slope[t] = a[0];
    }
}

// ---------- helpers ----------
__device__ __forceinline__ uint32_t smem_u32(const void* p) {
    uint32_t a;
    asm("{ .reg .u64 t; cvta.to.shared.u64 t, %1; cvt.u32.u64 %0, t; }" : "=r"(a) : "l"(p));
    return a;
}
__device__ __forceinline__ void cp16(uint32_t dst, const void* src) {
    asm volatile("cp.async.cg.shared.global [%0], [%1], 16;" :: "r"(dst), "l"(src) : "memory");
}
__device__ __forceinline__ void cp_commit() {
    asm volatile("cp.async.commit_group;" ::: "memory");
}
__device__ __forceinline__ void cp_wait1() {
    asm volatile("cp.async.wait_group 1;" ::: "memory");
}
__device__ __forceinline__ void cp_wait0() {
    asm volatile("cp.async.wait_group 0;" ::: "memory");
}

// Packed fp32x2 FMA (sm_100+): d = a*b + d
__device__ __forceinline__ void fma2(unsigned long long& acc,
                                     unsigned long long a, unsigned long long b) {
    asm("fma.rn.f32x2 %0, %1, %2, %0;" : "+l"(acc) : "l"(a), "l"(b));
}
__device__ __forceinline__ unsigned long long splat2(float v) {
    unsigned long long r;
    asm("mov.b64 %0, {%1, %1};" : "=l"(r) : "f"(v));
    return r;
}
__device__ __forceinline__ float2 unpack2(unsigned long long v) {
    float2 r;
    asm("mov.b64 {%0, %1}, %2;" : "=f"(r.x), "=f"(r.y) : "l"(v));
    return r;
}

// ---------- staging: one channel (x tile + weights) via cp.async ----------
// 90 rows (9 uv-planes x 10 h-rows), 10 x 16B chunks per row.
// smem col j holds global w = tw - 4 + j (cols 0..39). Edge chunks skipped
// (smem pre-zeroed once; OOB pattern channel-invariant).
__device__ __forceinline__ void stage_channel(const float* __restrict__ xc, int c,
                                              uint32_t sx_u32, uint32_t sw_u32,
                                              int u, int v, int th, int tw, int tid)
{
    #pragma unroll
    for (int i = 0; i < 4; i++) {
        int k = tid + i * 256;
        if (i < 3 || k < 900) {
            int row   = k / 10;
            int chunk = k - row * 10;
            int pidx  = row / 10;
            int r     = row - pidx * 10;
            int pa    = pidx / 3;
            int pb    = pidx - pa * 3;
            int gu = u + pa - 1;
            int gv = v + pb - 1;
            int gh = th + r - 1;
            int gw = tw - 4 + chunk * 4;          // global w of chunk start
            if ((unsigned)gu < NU && (unsigned)gv < NV && (unsigned)gh < NH &&
                (unsigned)gw < NW) {
                const float* src = xc + (((gu * 5 + gv) * NH + gh) << 6) + gw;
                uint32_t dst = sx_u32 + (uint32_t)(row * ROWF + chunk * 4) * 4u;
                cp16(dst, src);
            }
        }
    }
    if (tid < 216) {
        const float* src = g_wr + c * WF + tid * 4;
        cp16(sw_u32 + (uint32_t)tid * 16u, src);
    }
}

// ===== per-warp compute: one branch, one oc-half, 8 h-points x 4 oc =====
// acc[p][j]: h point p, channel pair (half*4 + 2j, +1).
// x col for (dw): wl + 4 + dw.

// uvx: taps (u, v, h); dw = 0
__device__ __forceinline__ void comp_uvx(const float* __restrict__ s_x,
                                         const float* __restrict__ s_w,
                                         int wl, unsigned long long (&acc)[8][2])
{
    #pragma unroll
    for (int ab = 0; ab < 9; ab++) {
        const float* col = s_x + ab * PLF + (wl + 4);
        unsigned long long xs[10];
        #pragma unroll
        for (int r = 0; r < 10; r++) xs[r] = splat2(col[r * ROWF]);
        #pragma unroll
        for (int kg = 0; kg < 3; kg++) {
            const float* wp = s_w + (ab * 3 + kg) * 8;
            ulonglong2 w01 = *(const ulonglong2*)wp;
            #pragma unroll
            for (int p = 0; p < 8; p++) {
                fma2(acc[p][0], xs[p + kg], w01.x);
                fma2(acc[p][1], xs[p + kg], w01.y);
            }
        }
    }
}

// uvy: taps (u, v, w); row p+1, col wl+3+kg
__device__ __forceinline__ void comp_uvy(const float* __restrict__ s_x,
                                         const float* __restrict__ s_w,
                                         int wl, unsigned long long (&acc)[8][2])
{
    #pragma unroll
    for (int ab = 0; ab < 9; ab++) {
        const float* plb = s_x + ab * PLF;
        #pragma unroll
        for (int kg = 0; kg < 3; kg++) {
            const float* col = plb + (wl + 3 + kg);
            const float* wp = s_w + 216 + (ab * 3 + kg) * 8;
            ulonglong2 w01 = *(const ulonglong2*)wp;
            #pragma unroll
            for (int p = 0; p < 8; p++) {
                unsigned long long xx = splat2(col[(p + 1) * ROWF]);
                fma2(acc[p][0], xx, w01.x);
                fma2(acc[p][1], xx, w01.y);
            }
        }
    }
}

// uxy (planes (ka,1), wbase 432) / vxy (planes (1,ka), wbase 648):
// taps (*, h, w): row p+kb, col wl+3+kg
__device__ __forceinline__ void comp_hw(const float* __restrict__ s_x,
                                        const float* __restrict__ s_w,
                                        int wl, int plane_base, int plane_step,
                                        int wbase, unsigned long long (&acc)[8][2])
{
    #pragma unroll
    for (int ka = 0; ka < 3; ka++) {
        const float* plb = s_x + (plane_base + ka * plane_step) * PLF;
        #pragma unroll
        for (int kg = 0; kg < 3; kg++) {
            const float* col = plb + (wl + 3 + kg);
            unsigned long long xs[10];
            #pragma unroll
            for (int r = 0; r < 10; r++) xs[r] = splat2(col[r * ROWF]);
            #pragma unroll
            for (int kb = 0; kb < 3; kb++) {
                const float* wp = s_w + wbase + ((ka * 3 + kb) * 3 + kg) * 8;
                ulonglong2 w01 = *(const ulonglong2*)wp;
                #pragma unroll
                for (int p = 0; p < 8; p++) {
                    fma2(acc[p][0], xs[p + kb], w01.x);
                    fma2(acc[p][1], xs[p + kb], w01.y);
                }
            }
        }
    }
}

// ===================== main kernel =====================
__global__ __launch_bounds__(256, 3)
void fe_kernel(const float* __restrict__ x, float* __restrict__ out)
{
    __shared__ __align__(16) float sm[2 * XF + 2 * WF];
    float* sx0 = sm;
    float* sx1 = sm + XF;
    float* sw0 = sm + 2 * XF;
    float* sw1 = sm + 2 * XF + WF;
    const uint32_t sx_u[2] = { smem_u32(sx0), smem_u32(sx1) };
    const uint32_t sw_u[2] = { smem_u32(sw0), smem_u32(sw1) };
    const float* sx_p[2] = { sx0, sx1 };
    const float* sw_p[2] = { sw0, sw1 };

    const int tid  = threadIdx.x;
    const int g    = tid >> 5;        // warp 0..7
    const int br   = g >> 1;          // branch 0..3
    const int half = g & 1;           // oc half 0..1
    const int wl   = tid & 31;        // w lane 0..31

    const int tile = blockIdx.x;              // 0..15
    const int tw   = (tile & 1) * TILE_W;
    const int th   = (tile >> 1) * TILE_H;    // 0..56
    const int uv   = blockIdx.y;              // 0..24
    const int u    = uv / 5, v = uv % 5;
    const int b    = blockIdx.z;              // 0..7

    // one-time zero (halo + channel-invariant OOB rows/chunks)
    float4* z = (float4*)sm;
    #pragma unroll
    for (int i = tid; i < (2 * XF + 2 * WF) / 4; i += 256)
        z[i] = make_float4(0.f, 0.f, 0.f, 0.f);
    __syncthreads();

    const float* xb = x + (size_t)b * (NC * CHSTRIDE);

    stage_channel(xb, 0, sx_u[0], sw_u[0], u, v, th, tw, tid);
    cp_commit();

    unsigned long long acc[8][2];
    #pragma unroll
    for (int p = 0; p < 8; p++) { acc[p][0] = 0ull; acc[p][1] = 0ull; }

    #pragma unroll 1
    for (int c = 0; c < NC; c++) {
        const int s = c & 1;
        if (c < NC - 1) {
            stage_channel(xb + (size_t)(c + 1) * CHSTRIDE, c + 1,
                          sx_u[s ^ 1], sw_u[s ^ 1], u, v, th, tw, tid);
            cp_commit();
            cp_wait1();
        } else {
            cp_wait0();
        }
        __syncthreads();

        const float* s_w = sw_p[s] + half * 4;   // oc half offset within tap
        if (br == 0)      comp_uvx(sx_p[s], s_w, wl, acc);
        else if (br == 1) comp_uvy(sx_p[s], s_w, wl, acc);
        else if (br == 2) comp_hw(sx_p[s], s_w, wl, 1, 3, 432, acc); // uxy
        else              comp_hw(sx_p[s], s_w, wl, 3, 1, 648, acc); // vxy
        __syncthreads();
    }

    // ---- epilogue: bias + PReLU + store ----
    const float slope = g_slope[br];
    const int ocb = br * 8 + half * 4;
    const size_t base0 = (size_t)b * 32 * CHSTRIDE + (size_t)ocb * CHSTRIDE +
                         (size_t)uv * (NH * NW) + (size_t)th * NW + (size_t)(tw + wl);
    #pragma unroll
    for (int j = 0; j < 2; j++) {
        const float b0 = g_bias[ocb + j * 2];
        const float b1 = g_bias[ocb + j * 2 + 1];
        const size_t cb0 = base0 + (size_t)(j * 2) * CHSTRIDE;
        const size_t cb1 = base0 + (size_t)(j * 2 + 1) * CHSTRIDE;
        #pragma unroll
        for (int p = 0; p < 8; p++) {
            float2 y = unpack2(acc[p][j]);
            float y0 = y.x + b0;
            float y1 = y.y + b1;
            y0 = (y0 >= 0.f) ? y0 : slope * y0;
            y1 = (y1 >= 0.f) ? y1 : slope * y1;
            out[cb0 + (size_t)p * NW] = y0;
            out[cb1 + (size_t)p * NW] = y1;
        }
    }
}

extern "C" void kernel_launch(void* const* d_in, const int* in_sizes, int n_in,
                              void* d_out, int out_size)
{
    const float* x = (const float*)d_in[0];

    prep_kernel<<<(NC * WF + 255) / 256, 256>>>(
        (const float*)d_in[1], (const float*)d_in[4],
        (const float*)d_in[7], (const float*)d_in[10],
        (const float*)d_in[2], (const float*)d_in[5],
        (const float*)d_in[8], (const float*)d_in[11],
        (const float*)d_in[3], (const float*)d_in[6],
        (const float*)d_in[9], (const float*)d_in[12]);

    dim3 grid(16, 25, 8);   // (hw tiles, uv, batch)
    fe_kernel<<<grid, 256>>>(x, (float*)d_out);
}